// round 9
// baseline (speedup 1.0000x reference)
#include <cuda_runtime.h>
#include <cuda_bf16.h>
#include <math.h>

#define B_   16
#define S_   64
#define T_   64
#define TM1_ 63
#define H_   512
#define H3_  1536
#define V_   32000
#define ME_  (B_*S_)     // 1024 encoder rows
#define MD_  (B_*TM1_)   // 1008 decoder rows
#define MP_  1024        // padded M for logits MMA
#define NCTA 128

// ---------------- device scratch (no allocation allowed) ----------------
__device__ float g_emb_x[ME_*H_];
__device__ float g_emb_y[MD_*H_];
__device__ float g_gi_enc[ME_*H3_];
__device__ float g_gi_dec[MD_*H3_];
__device__ float g_enc_out[ME_*H_];
__device__ float g_h[2][B_*H_];
__device__ float g_cat[MD_*2*H_];
__device__ float g_dseq[MD_*H_];
__device__ float g_rownll[MD_];

__device__ __nv_bfloat16 g_whi[(long)V_*H_];   // W_out hi
__device__ __nv_bfloat16 g_wlo[(long)V_*H_];   // W_out lo
__device__ __nv_bfloat16 g_dhi[MP_*H_];        // d hi (padded)
__device__ __nv_bfloat16 g_dlo[MP_*H_];        // d lo

__device__ unsigned g_cnt0[8*32];              // 8 group counters, 128B apart
__device__ unsigned g_cnt1 = 0;
__device__ volatile unsigned g_gen2 = 0;

// ---------------- two-level software grid barrier (128 CTAs co-resident) ----------------
// Arrivals: 16 per group counter (8 groups in parallel) + 8 level-2 => ~700 cyc
// vs ~4100 for 128 serialized same-address atomics.
__device__ __forceinline__ void grid_bar2() {
    __threadfence();
    __syncthreads();
    if (threadIdx.x == 0) {
        unsigned gen = g_gen2;                 // MUST read before arrival
        unsigned grp = blockIdx.x & 7u;
        if (atomicAdd(&g_cnt0[grp * 32], 1u) == 15u) {
            atomicExch(&g_cnt0[grp * 32], 0u); // safe: no re-arrival until release
            if (atomicAdd(&g_cnt1, 1u) == 7u) {
                atomicExch(&g_cnt1, 0u);
                __threadfence();
                atomicAdd((unsigned*)&g_gen2, 1u);   // release
            }
        }
        while (g_gen2 == gen) { }              // tight spin; same-line L2 broadcast
        __threadfence();
    }
    __syncthreads();
}

// ---------------- embedding gather ----------------
__global__ void embed_kernel(const int* __restrict__ x, const int* __restrict__ y,
                             const float* __restrict__ emb_enc,
                             const float* __restrict__ emb_dec) {
    int i = blockIdx.x * blockDim.x + threadIdx.x;
    const int n1 = ME_ * H_;
    const int n2 = MD_ * H_;
    if (i < n1) {
        int row = i / H_, h = i % H_;
        g_emb_x[i] = emb_enc[(long)x[row] * H_ + h];
    } else if (i < n1 + n2) {
        int j = i - n1;
        int row = j / H_, h = j % H_;
        int b = row / TM1_, t = row % TM1_;
        g_emb_y[j] = emb_dec[(long)y[b * T_ + t] * H_ + h];
    }
}

// ---------------- generic fp32 GEMM (R2-proven): C = act(A*Bw^T + bias) ----------------
__global__ void sgemm_nt(int a_sel, const float* __restrict__ Bw,
                         const float* __restrict__ bias, float* __restrict__ Cext,
                         int c_sel, int M, int N, int K, int act) {
    __shared__ float As[16][64];
    __shared__ float Bs[16][64];
    const float* A = (a_sel == 0) ? g_emb_x : (a_sel == 1) ? g_emb_y
                   : (a_sel == 2) ? g_dseq : g_cat;
    float* C = (c_sel == 0) ? g_gi_enc : (c_sel == 1) ? g_gi_dec
             : (c_sel == 2) ? Cext : g_dseq;

    int tx = threadIdx.x & 15;
    int ty = threadIdx.x >> 4;
    int m0 = blockIdx.y * 64, n0 = blockIdx.x * 64;
    int lr = threadIdx.x >> 2;
    int lc = (threadIdx.x & 3) * 4;

    float acc[4][4] = {};
    for (int kc = 0; kc < K; kc += 16) {
        float4 av = make_float4(0.f, 0.f, 0.f, 0.f);
        if (m0 + lr < M) av = *(const float4*)&A[(long)(m0 + lr) * K + kc + lc];
        As[lc + 0][lr] = av.x; As[lc + 1][lr] = av.y;
        As[lc + 2][lr] = av.z; As[lc + 3][lr] = av.w;
        float4 bv = *(const float4*)&Bw[(long)(n0 + lr) * K + kc + lc];
        Bs[lc + 0][lr] = bv.x; Bs[lc + 1][lr] = bv.y;
        Bs[lc + 2][lr] = bv.z; Bs[lc + 3][lr] = bv.w;
        __syncthreads();
#pragma unroll
        for (int k = 0; k < 16; k++) {
            float4 a = *(float4*)&As[k][tx * 4];
            float4 b = *(float4*)&Bs[k][ty * 4];
            acc[0][0] += a.x * b.x; acc[0][1] += a.x * b.y; acc[0][2] += a.x * b.z; acc[0][3] += a.x * b.w;
            acc[1][0] += a.y * b.x; acc[1][1] += a.y * b.y; acc[1][2] += a.y * b.z; acc[1][3] += a.y * b.w;
            acc[2][0] += a.z * b.x; acc[2][1] += a.z * b.y; acc[2][2] += a.z * b.z; acc[2][3] += a.z * b.w;
            acc[3][0] += a.w * b.x; acc[3][1] += a.w * b.y; acc[3][2] += a.w * b.z; acc[3][3] += a.w * b.w;
        }
        __syncthreads();
    }
#pragma unroll
    for (int j = 0; j < 4; j++) {
        float bj = bias[n0 + ty * 4 + j];
#pragma unroll
        for (int i = 0; i < 4; i++) {
            int row = m0 + tx * 4 + i;
            if (row < M) {
                float v = acc[i][j] + bj;
                if (act) v = tanhf(v);
                C[(long)row * N + n0 + ty * 4 + j] = v;
            }
        }
    }
}

// ---------------- persistent GRU recurrence v5 (low-LDS layout + fast barrier) ----------------
__global__ void __launch_bounds__(256, 1)
recurrence_kernel(const float* __restrict__ Whh_e, const float* __restrict__ bhh_e,
                  const float* __restrict__ Whh_d, const float* __restrict__ bhh_d) {
    extern __shared__ float sm[];
    float* we   = sm;                  // [12][512] = 6144
    float* wd   = we + 6144;           // 6144
    float* hs   = wd + 6144;           // [16][520] = 8320
    float* red  = hs + 8320;           // [192][68] = 13056
    float* red2 = red + 13056;         // [3][64] = 192

    const int tid = threadIdx.x;
    const int cta = blockIdx.x;
    const int jbase = cta * 4;
    const int jj = tid >> 6, ks = tid & 63;

    // load weight slices once: row r = g*4+j2
    for (int v = tid; v < 12 * 128; v += 256) {
        int r = v >> 7, c = v & 127;
        int g = r >> 2, j2 = r & 3;
        long src = ((long)(g * H_ + jbase + j2) * H_) / 4 + c;
        ((float4*)we)[r * 128 + c] = ((const float4*)Whh_e)[src];
        ((float4*)wd)[r * 128 + c] = ((const float4*)Whh_d)[src];
    }

    // reduction-thread constants (o < 192): o -> (og, ojj, ob)
    const int o = tid;
    const int og = o >> 6, ojj = (o & 63) >> 4, ob = o & 15;
    float obe = 0.f, obd = 0.f;
    if (o < 192) {
        int oj = jbase + ojj;
        obe = bhh_e[og * H_ + oj];
        obd = bhh_d[og * H_ + oj];
    }
    // final-h thread constants (tid < 64)
    const int fjj = tid >> 4, fb = tid & 15;
    const int fj = jbase + fjj;

    for (int v = tid; v < 8320; v += 256) hs[v] = 0.f;
    __syncthreads();

    // prefetch gi for step 0
    float gi0 = 0.f, gi1 = 0.f, gi2 = 0.f;
    if (tid < 64) {
        const float* gi = &g_gi_enc[(long)(fb * S_) * H3_];
        gi0 = __ldcg(&gi[fj]);
        gi1 = __ldcg(&gi[H_ + fj]);
        gi2 = __ldcg(&gi[2 * H_ + fj]);
    }

    int cur = 0;
    for (int step = 0; step < 127; step++) {
        const int enc = (step < 64);
        const int t = enc ? step : step - 64;

        if (step > 0) {
            for (int v = tid; v < 2048; v += 256) {
                int bb = v >> 7, c4 = v & 127;
                float4 hv = __ldcg(((const float4*)g_h[cur]) + v);
                *(float4*)&hs[bb * 520 + c4 * 4] = hv;
            }
        }
        __syncthreads();

        const float* W = enc ? we : wd;
        float a0[16], a1[16], a2[16];
#pragma unroll
        for (int b = 0; b < 16; b++) { a0[b] = 0.f; a1[b] = 0.f; a2[b] = 0.f; }

#pragma unroll
        for (int c = 0; c < 2; c++) {
            const int k0 = c * 256 + ks * 4;
            float4 w0 = *(const float4*)&W[(0 * 4 + jj) * 512 + k0];
            float4 w1 = *(const float4*)&W[(1 * 4 + jj) * 512 + k0];
            float4 w2 = *(const float4*)&W[(2 * 4 + jj) * 512 + k0];
#pragma unroll
            for (int b = 0; b < 16; b++) {
                float4 hv = *(const float4*)&hs[b * 520 + k0];
                a0[b] += w0.x * hv.x + w0.y * hv.y + w0.z * hv.z + w0.w * hv.w;
                a1[b] += w1.x * hv.x + w1.y * hv.y + w1.z * hv.z + w1.w * hv.w;
                a2[b] += w2.x * hv.x + w2.y * hv.y + w2.z * hv.z + w2.w * hv.w;
            }
        }

#pragma unroll
        for (int b = 0; b < 16; b++) {
            red[((0 * 4 + jj) * 16 + b) * 68 + ks] = a0[b];
            red[((1 * 4 + jj) * 16 + b) * 68 + ks] = a1[b];
            red[((2 * 4 + jj) * 16 + b) * 68 + ks] = a2[b];
        }
        __syncthreads();

        if (o < 192) {
            const float* rp = &red[o * 68];
            float4 s4 = make_float4(0.f, 0.f, 0.f, 0.f);
#pragma unroll
            for (int i = 0; i < 16; i++) {
                float4 v = *(const float4*)&rp[i * 4];
                s4.x += v.x; s4.y += v.y; s4.z += v.z; s4.w += v.w;
            }
            float s = (s4.x + s4.y) + (s4.z + s4.w);
            red2[og * 64 + ojj * 16 + ob] = s + (enc ? obe : obd);
        }
        __syncthreads();

        if (tid < 64) {
            float hr = red2[0 * 64 + tid];
            float hz = red2[1 * 64 + tid];
            float hn = red2[2 * 64 + tid];
            float r = 1.f / (1.f + expf(-(gi0 + hr)));
            float z = 1.f / (1.f + expf(-(gi1 + hz)));
            float n = tanhf(gi2 + r * hn);
            float hprev = hs[fb * 520 + fj];
            float h = (1.f - z) * n + z * hprev;
            g_h[cur ^ 1][fb * H_ + fj] = h;
            if (enc) g_enc_out[(long)(fb * S_ + t) * H_ + fj] = h;
            else     g_cat[(long)(fb * TM1_ + t) * 2 * H_ + fj] = h;
        }

        // prefetch gi for NEXT step before the barrier (latency hides under wait)
        if (step + 1 < 127 && tid < 64) {
            const int enc2 = (step + 1 < 64);
            const int t2 = enc2 ? step + 1 : step + 1 - 64;
            const float* gi = enc2 ? &g_gi_enc[(long)(fb * S_ + t2) * H3_]
                                   : &g_gi_dec[(long)(fb * TM1_ + t2) * H3_];
            gi0 = __ldcg(&gi[fj]);
            gi1 = __ldcg(&gi[H_ + fj]);
            gi2 = __ldcg(&gi[2 * H_ + fj]);
        }

        cur ^= 1;
        if (step != 126) grid_bar2();
    }
}

// ---------------- batched attention (R2-proven) ----------------
__global__ void attn_batch() {
    __shared__ float hsh[H_];
    __shared__ float sc[S_];
    __shared__ float wgt[S_];
    int row = blockIdx.x;
    int b = row / TM1_;
    int tid = threadIdx.x;
    const float* enc = g_enc_out + (long)b * S_ * H_;
    const float* hrow = &g_cat[(long)row * 2 * H_];

    for (int v = tid; v < H_; v += 256) hsh[v] = hrow[v];
    __syncthreads();

    int s = tid >> 2, q = tid & 3;
    {
        const float* e = enc + s * H_ + q * 128;
        const float* hq = hsh + q * 128;
        float p = 0.f;
#pragma unroll
        for (int k = 0; k < 128; k += 4) {
            float4 ev = *(const float4*)&e[k];
            float4 hv = *(const float4*)&hq[k];
            p += ev.x * hv.x + ev.y * hv.y + ev.z * hv.z + ev.w * hv.w;
        }
        p += __shfl_xor_sync(0xffffffffu, p, 1);
        p += __shfl_xor_sync(0xffffffffu, p, 2);
        if (q == 0) sc[s] = p;
    }
    __syncthreads();
    if (tid < 32) {
        float a0 = sc[tid], a1 = sc[tid + 32];
        float m = fmaxf(a0, a1);
        for (int o = 16; o; o >>= 1) m = fmaxf(m, __shfl_xor_sync(0xffffffffu, m, o));
        float e0 = expf(a0 - m), e1 = expf(a1 - m);
        float ss = e0 + e1;
        for (int o = 16; o; o >>= 1) ss += __shfl_xor_sync(0xffffffffu, ss, o);
        wgt[tid] = e0 / ss;
        wgt[tid + 32] = e1 / ss;
    }
    __syncthreads();
    {
        int k = tid, k2 = tid + 256;
        float acc = 0.f, acc2 = 0.f;
#pragma unroll 8
        for (int s2 = 0; s2 < S_; s2++) {
            float w = wgt[s2];
            acc  += w * enc[s2 * H_ + k];
            acc2 += w * enc[s2 * H_ + k2];
        }
        g_cat[(long)row * 2 * H_ + H_ + k]  = acc;
        g_cat[(long)row * 2 * H_ + H_ + k2] = acc2;
    }
}

// ---------------- bf16 split conversions ----------------
__device__ __forceinline__ void split_bf(float x, __nv_bfloat16& hi, __nv_bfloat16& lo) {
    hi = __float2bfloat16_rn(x);
    lo = __float2bfloat16_rn(x - __bfloat162float(hi));
}

__global__ void convert_w(const float* __restrict__ W) {
    long i = ((long)blockIdx.x * blockDim.x + threadIdx.x) * 4;
    if (i >= (long)V_ * H_) return;
    float4 v = *(const float4*)&W[i];
    __nv_bfloat16 h0, h1, h2, h3, l0, l1, l2, l3;
    split_bf(v.x, h0, l0); split_bf(v.y, h1, l1);
    split_bf(v.z, h2, l2); split_bf(v.w, h3, l3);
    *(__nv_bfloat162*)&g_whi[i]     = __nv_bfloat162(h0, h1);
    *(__nv_bfloat162*)&g_whi[i + 2] = __nv_bfloat162(h2, h3);
    *(__nv_bfloat162*)&g_wlo[i]     = __nv_bfloat162(l0, l1);
    *(__nv_bfloat162*)&g_wlo[i + 2] = __nv_bfloat162(l2, l3);
}

__global__ void convert_d() {
    long i = ((long)blockIdx.x * blockDim.x + threadIdx.x) * 4;
    if (i >= (long)MP_ * H_) return;
    int row = (int)(i / H_);
    float4 v = make_float4(0.f, 0.f, 0.f, 0.f);
    if (row < MD_) v = *(const float4*)&g_dseq[i];
    __nv_bfloat16 h0, h1, h2, h3, l0, l1, l2, l3;
    split_bf(v.x, h0, l0); split_bf(v.y, h1, l1);
    split_bf(v.z, h2, l2); split_bf(v.w, h3, l3);
    *(__nv_bfloat162*)&g_dhi[i]     = __nv_bfloat162(h0, h1);
    *(__nv_bfloat162*)&g_dhi[i + 2] = __nv_bfloat162(h2, h3);
    *(__nv_bfloat162*)&g_dlo[i]     = __nv_bfloat162(l0, l1);
    *(__nv_bfloat162*)&g_dlo[i + 2] = __nv_bfloat162(l2, l3);
}

// ---------------- mma.sync helpers ----------------
__device__ __forceinline__ void ldm_x4(unsigned& r0, unsigned& r1, unsigned& r2, unsigned& r3,
                                       unsigned addr) {
    asm volatile("ldmatrix.sync.aligned.m8n8.x4.shared.b16 {%0,%1,%2,%3}, [%4];"
                 : "=r"(r0), "=r"(r1), "=r"(r2), "=r"(r3) : "r"(addr));
}
__device__ __forceinline__ void ldm_x2(unsigned& r0, unsigned& r1, unsigned addr) {
    asm volatile("ldmatrix.sync.aligned.m8n8.x2.shared.b16 {%0,%1}, [%2];"
                 : "=r"(r0), "=r"(r1) : "r"(addr));
}
__device__ __forceinline__ void mma_bf16(float* c, const unsigned* a, const unsigned* b) {
    asm volatile("mma.sync.aligned.m16n8k16.row.col.f32.bf16.bf16.f32 "
                 "{%0,%1,%2,%3}, {%4,%5,%6,%7}, {%8,%9}, {%0,%1,%2,%3};"
                 : "+f"(c[0]), "+f"(c[1]), "+f"(c[2]), "+f"(c[3])
                 : "r"(a[0]), "r"(a[1]), "r"(a[2]), "r"(a[3]), "r"(b[0]), "r"(b[1]));
}

// ---------------- split-bf16 logits GEMM (R4-proven) ----------------
#define LPAD 40
__global__ void __launch_bounds__(256, 1)
mma_logits(const float* __restrict__ bias, float* __restrict__ out) {
    extern __shared__ __nv_bfloat16 smem_bf[];
    __nv_bfloat16* Ah = smem_bf;                    // [2][128*LPAD]
    __nv_bfloat16* Al = Ah + 2 * 128 * LPAD;
    __nv_bfloat16* Bh = Al + 2 * 128 * LPAD;
    __nv_bfloat16* Bl = Bh + 2 * 128 * LPAD;

    const int tid = threadIdx.x;
    const int warp = tid >> 5, lane = tid & 31;
    const int wm = warp >> 2, wn = warp & 3;
    const int m0 = blockIdx.y * 128, n0 = blockIdx.x * 128;

    const int lrow = tid >> 1;
    const int lcol = (tid & 1) * 16;

    const __nv_bfloat16* Ahp = g_dhi + (long)(m0 + lrow) * H_ + lcol;
    const __nv_bfloat16* Alp = g_dlo + (long)(m0 + lrow) * H_ + lcol;
    const __nv_bfloat16* Bhp = g_whi + (long)(n0 + lrow) * H_ + lcol;
    const __nv_bfloat16* Blp = g_wlo + (long)(n0 + lrow) * H_ + lcol;
    const int sdst = lrow * LPAD + lcol;

    float acc[4][4][4];
#pragma unroll
    for (int i = 0; i < 4; i++)
#pragma unroll
        for (int j = 0; j < 4; j++)
#pragma unroll
            for (int q = 0; q < 4; q++) acc[i][j][q] = 0.f;

    uint4 rAh[2], rAl[2], rBh[2], rBl[2];
#pragma unroll
    for (int u = 0; u < 2; u++) {
        rAh[u] = *(const uint4*)(Ahp + u * 8);
        rAl[u] = *(const uint4*)(Alp + u * 8);
        rBh[u] = *(const uint4*)(Bhp + u * 8);
        rBl[u] = *(const uint4*)(Blp + u * 8);
    }
#pragma unroll
    for (int u = 0; u < 2; u++) {
        *(uint4*)&Ah[sdst + u * 8] = rAh[u];
        *(uint4*)&Al[sdst + u * 8] = rAl[u];
        *(uint4*)&Bh[sdst + u * 8] = rBh[u];
        *(uint4*)&Bl[sdst + u * 8] = rBl[u];
    }
    __syncthreads();

    const int a_row = lane & 15, a_colh = (lane >> 4) * 8;
    const int b_row = lane & 7,  b_colh = ((lane >> 3) & 1) * 8;

    for (int c = 0; c < 16; c++) {
        const int buf = c & 1;
        if (c + 1 < 16) {
            const int ko = (c + 1) * 32;
#pragma unroll
            for (int u = 0; u < 2; u++) {
                rAh[u] = *(const uint4*)(Ahp + ko + u * 8);
                rAl[u] = *(const uint4*)(Alp + ko + u * 8);
                rBh[u] = *(const uint4*)(Bhp + ko + u * 8);
                rBl[u] = *(const uint4*)(Blp + ko + u * 8);
            }
        }

        const __nv_bfloat16* Ahb = Ah + buf * 128 * LPAD;
        const __nv_bfloat16* Alb = Al + buf * 128 * LPAD;
        const __nv_bfloat16* Bhb = Bh + buf * 128 * LPAD;
        const __nv_bfloat16* Blb = Bl + buf * 128 * LPAD;

#pragma unroll
        for (int kk = 0; kk < 32; kk += 16) {
            unsigned fAh[4][4], fAl[4][4], fBh[4][2], fBl[4][2];
#pragma unroll
            for (int mi = 0; mi < 4; mi++) {
                int r = wm * 64 + mi * 16 + a_row;
                unsigned ah = (unsigned)__cvta_generic_to_shared(&Ahb[r * LPAD + kk + a_colh]);
                unsigned al = (unsigned)__cvta_generic_to_shared(&Alb[r * LPAD + kk + a_colh]);
                ldm_x4(fAh[mi][0], fAh[mi][1], fAh[mi][2], fAh[mi][3], ah);
                ldm_x4(fAl[mi][0], fAl[mi][1], fAl[mi][2], fAl[mi][3], al);
            }
#pragma unroll
            for (int ni = 0; ni < 4; ni++) {
                int r = wn * 32 + ni * 8 + b_row;
                unsigned bh = (unsigned)__cvta_generic_to_shared(&Bhb[r * LPAD + kk + b_colh]);
                unsigned bl = (unsigned)__cvta_generic_to_shared(&Blb[r * LPAD + kk + b_colh]);
                ldm_x2(fBh[ni][0], fBh[ni][1], bh);
                ldm_x2(fBl[ni][0], fBl[ni][1], bl);
            }
#pragma unroll
            for (int mi = 0; mi < 4; mi++)
#pragma unroll
                for (int ni = 0; ni < 4; ni++) {
                    mma_bf16(acc[mi][ni], fAh[mi], fBh[ni]);
                    mma_bf16(acc[mi][ni], fAh[mi], fBl[ni]);
                    mma_bf16(acc[mi][ni], fAl[mi], fBh[ni]);
                }
        }
        __syncthreads();
        if (c + 1 < 16) {
            const int nb = (c + 1) & 1;
            __nv_bfloat16* dAh = Ah + nb * 128 * LPAD;
            __nv_bfloat16* dAl = Al + nb * 128 * LPAD;
            __nv_bfloat16* dBh = Bh + nb * 128 * LPAD;
            __nv_bfloat16* dBl = Bl + nb * 128 * LPAD;
#pragma unroll
            for (int u = 0; u < 2; u++) {
                *(uint4*)&dAh[sdst + u * 8] = rAh[u];
                *(uint4*)&dAl[sdst + u * 8] = rAl[u];
                *(uint4*)&dBh[sdst + u * 8] = rBh[u];
                *(uint4*)&dBl[sdst + u * 8] = rBl[u];
            }
            __syncthreads();
        }
    }

#pragma unroll
    for (int ni = 0; ni < 4; ni++) {
        int col = n0 + wn * 32 + ni * 8 + (lane & 3) * 2;
        float2 bj = *(const float2*)&bias[col];
#pragma unroll
        for (int mi = 0; mi < 4; mi++) {
            int r0 = m0 + wm * 64 + mi * 16 + (lane >> 2);
            if (r0 < MD_) {
                float2 v = make_float2(acc[mi][ni][0] + bj.x, acc[mi][ni][1] + bj.y);
                *(float2*)&out[(long)r0 * V_ + col] = v;
            }
            int r1 = r0 + 8;
            if (r1 < MD_) {
                float2 v = make_float2(acc[mi][ni][2] + bj.x, acc[mi][ni][3] + bj.y);
                *(float2*)&out[(long)r1 * V_ + col] = v;
            }
        }
    }
}

// ---------------- loss: single-pass online softmax NLL ----------------
__global__ void nll_rows(const float* __restrict__ logits, const int* __restrict__ y) {
    __shared__ float mred[256], sred[256];
    int row = blockIdx.x;
    int b = row / TM1_, t = row % TM1_;
    int tgt = y[b * T_ + t + 1];
    const float* L = logits + (long)row * V_;

    float m = -INFINITY, s = 0.f;
    for (int i = threadIdx.x * 4; i < V_; i += 1024) {
        float4 v4 = __ldcg((const float4*)&L[i]);
        float vv[4] = {v4.x, v4.y, v4.z, v4.w};
#pragma unroll
        for (int q = 0; q < 4; q++) {
            float v = vv[q];
            if (v > m) { s *= expf(m - v); m = v; }
            s += expf(v - m);
        }
    }
    mred[threadIdx.x] = m; sred[threadIdx.x] = s;
    __syncthreads();
    for (int o = 128; o; o >>= 1) {
        if (threadIdx.x < o) {
            float m1 = mred[threadIdx.x], s1 = sred[threadIdx.x];
            float m2 = mred[threadIdx.x + o], s2 = sred[threadIdx.x + o];
            float M = fmaxf(m1, m2);
            mred[threadIdx.x] = M;
            sred[threadIdx.x] = s1 * expf(m1 - M) + s2 * expf(m2 - M);
        }
        __syncthreads();
    }
    if (threadIdx.x == 0) g_rownll[row] = logf(sred[0]) + mred[0] - L[tgt];
}

__global__ void loss_reduce(float* __restrict__ out) {
    __shared__ float red[256];
    float ss = 0.f;
    for (int i = threadIdx.x; i < MD_; i += 256) ss += g_rownll[i];
    red[threadIdx.x] = ss;
    __syncthreads();
    for (int o = 128; o; o >>= 1) {
        if (threadIdx.x < o) red[threadIdx.x] += red[threadIdx.x + o];
        __syncthreads();
    }
    if (threadIdx.x == 0) out[0] = red[0] / (float)MD_;
}

// ---------------- host ----------------
extern "C" void kernel_launch(void* const* d_in, const int* in_sizes, int n_in,
                              void* d_out, int out_size) {
    const int*   x       = (const int*)d_in[0];
    const int*   y       = (const int*)d_in[1];
    const float* emb_enc = (const float*)d_in[2];
    const float* W_ih_e  = (const float*)d_in[3];
    const float* W_hh_e  = (const float*)d_in[4];
    const float* b_ih_e  = (const float*)d_in[5];
    const float* b_hh_e  = (const float*)d_in[6];
    const float* emb_dec = (const float*)d_in[7];
    const float* W_ih_d  = (const float*)d_in[8];
    const float* W_hh_d  = (const float*)d_in[9];
    const float* b_ih_d  = (const float*)d_in[10];
    const float* b_hh_d  = (const float*)d_in[11];
    const float* W_c     = (const float*)d_in[12];
    const float* b_c     = (const float*)d_in[13];
    const float* W_out   = (const float*)d_in[14];
    const float* b_out   = (const float*)d_in[15];
    float* out = (float*)d_out;

    // 1. embeddings + W_out bf16 split (independent)
    {
        int total = ME_ * H_ + MD_ * H_;
        embed_kernel<<<(total + 255) / 256, 256>>>(x, y, emb_enc, emb_dec);
    }
    {
        long n4 = (long)V_ * H_ / 4;
        convert_w<<<(int)((n4 + 255) / 256), 256>>>(W_out);
    }

    // 2. input-side gate precompute
    sgemm_nt<<<dim3(H3_ / 64, ME_ / 64), 256>>>(0, W_ih_e, b_ih_e, nullptr, 0, ME_, H3_, H_, 0);
    sgemm_nt<<<dim3(H3_ / 64, (MD_ + 63) / 64), 256>>>(1, W_ih_d, b_ih_d, nullptr, 1, MD_, H3_, H_, 0);

    // 3. persistent recurrence (low-LDS layout + two-level barrier)
    {
        const int smem = (6144 * 2 + 8320 + 13056 + 192) * sizeof(float); // 135808 B
        cudaFuncSetAttribute(recurrence_kernel,
                             cudaFuncAttributeMaxDynamicSharedMemorySize, smem);
        recurrence_kernel<<<NCTA, 256, smem>>>(W_hh_e, b_hh_e, W_hh_d, b_hh_d);
    }

    // 4. batched attention
    attn_batch<<<MD_, 256>>>();

    // 5. d = tanh(concat(h, attn) @ W_c^T + b_c)
    sgemm_nt<<<dim3(H_ / 64, (MD_ + 63) / 64), 256>>>(3, W_c, b_c, nullptr, 3, MD_, H_, 2 * H_, 1);

    // 6. split d to bf16, then tensor-core logits GEMM -> d_out
    {
        long n4 = (long)MP_ * H_ / 4;
        convert_d<<<(int)((n4 + 255) / 256), 256>>>();
    }
    {
        const int smem = 8 * 128 * LPAD * sizeof(__nv_bfloat16);  // 81920 B
        cudaFuncSetAttribute(mma_logits,
                             cudaFuncAttributeMaxDynamicSharedMemorySize, smem);
        mma_logits<<<dim3(V_ / 128, MP_ / 128), 256, smem>>>(b_out, out);
    }

    // 7. loss
    if (out_size >= MD_ * V_ + 1) {
        nll_rows<<<MD_, 256>>>(out, y);
        loss_reduce<<<1, 256>>>(out + (long)MD_ * V_);
    }
}

// round 11
// speedup vs baseline: 1.1289x; 1.1289x over previous
#include <cuda_runtime.h>
#include <cuda_bf16.h>
#include <math.h>

#define B_   16
#define S_   64
#define T_   64
#define TM1_ 63
#define H_   512
#define H3_  1536
#define V_   32000
#define ME_  (B_*S_)     // 1024 encoder rows
#define MD_  (B_*TM1_)   // 1008 decoder rows
#define MP_  1024        // padded M for MMA
#define NCTA 128

// ---------------- device scratch (no allocation allowed) ----------------
__device__ float g_emb_x[ME_*H_];
__device__ float g_emb_y[MD_*H_];
__device__ float g_gi_enc[ME_*H3_];
__device__ float g_gi_dec[MD_*H3_];
__device__ float g_enc_out[ME_*H_];
__device__ float g_h[2][B_*H_];
__device__ float g_cat[MD_*2*H_];
__device__ float g_dseq[MD_*H_];
__device__ float g_rownll[MD_];

// split-bf16 operand buffers
__device__ __nv_bfloat16 g_whi[(long)V_*H_], g_wlo[(long)V_*H_];     // W_out
__device__ __nv_bfloat16 g_dhi[MP_*H_],      g_dlo[MP_*H_];          // d (padded)
__device__ __nv_bfloat16 g_exh[ME_*H_],      g_exl[ME_*H_];          // emb_x
__device__ __nv_bfloat16 g_eyh[MP_*H_],      g_eyl[MP_*H_];          // emb_y (padded)
__device__ __nv_bfloat16 g_wieh[H3_*H_],     g_wiel[H3_*H_];         // W_ih_e
__device__ __nv_bfloat16 g_widh[H3_*H_],     g_widl[H3_*H_];         // W_ih_d
__device__ __nv_bfloat16 g_wch[H_*2*H_],     g_wcl[H_*2*H_];         // W_c
__device__ __nv_bfloat16 g_cath[MP_*2*H_],   g_catl[MP_*2*H_];       // concat (padded)

__device__ unsigned g_cnt = 0;
__device__ unsigned g_gen = 0;

// ---------------- software grid barrier (R7-proven flat version) ----------------
__device__ __forceinline__ void grid_bar() {
    __threadfence();
    __syncthreads();
    if (threadIdx.x == 0) {
        unsigned g = *(volatile unsigned*)&g_gen;
        if (atomicAdd(&g_cnt, 1u) == NCTA - 1) {
            g_cnt = 0;
            __threadfence();
            atomicExch(&g_gen, g + 1u);
        } else {
            while (*(volatile unsigned*)&g_gen == g) __nanosleep(32);
        }
        __threadfence();
    }
    __syncthreads();
}

// ---------------- embedding gather ----------------
__global__ void embed_kernel(const int* __restrict__ x, const int* __restrict__ y,
                             const float* __restrict__ emb_enc,
                             const float* __restrict__ emb_dec) {
    int i = blockIdx.x * blockDim.x + threadIdx.x;
    const int n1 = ME_ * H_;
    const int n2 = MD_ * H_;
    if (i < n1) {
        int row = i / H_, h = i % H_;
        g_emb_x[i] = emb_enc[(long)x[row] * H_ + h];
    } else if (i < n1 + n2) {
        int j = i - n1;
        int row = j / H_, h = j % H_;
        int b = row / TM1_, t = row % TM1_;
        g_emb_y[j] = emb_dec[(long)y[b * T_ + t] * H_ + h];
    }
}

// ---------------- generic split-bf16 conversion (with row padding) ----------------
__device__ __forceinline__ void split_bf(float x, __nv_bfloat16& hi, __nv_bfloat16& lo) {
    hi = __float2bfloat16_rn(x);
    lo = __float2bfloat16_rn(x - __bfloat162float(hi));
}

__global__ void convert_split(const float* __restrict__ src,
                              __nv_bfloat16* __restrict__ hi,
                              __nv_bfloat16* __restrict__ lo,
                              int rows_src, long total, int cols) {
    long i = ((long)blockIdx.x * blockDim.x + threadIdx.x) * 4;
    if (i >= total) return;
    int row = (int)(i / cols);
    float4 v = make_float4(0.f, 0.f, 0.f, 0.f);
    if (row < rows_src) v = *(const float4*)&src[i];
    __nv_bfloat16 h0, h1, h2, h3, l0, l1, l2, l3;
    split_bf(v.x, h0, l0); split_bf(v.y, h1, l1);
    split_bf(v.z, h2, l2); split_bf(v.w, h3, l3);
    *(__nv_bfloat162*)&hi[i]     = __nv_bfloat162(h0, h1);
    *(__nv_bfloat162*)&hi[i + 2] = __nv_bfloat162(h2, h3);
    *(__nv_bfloat162*)&lo[i]     = __nv_bfloat162(l0, l1);
    *(__nv_bfloat162*)&lo[i + 2] = __nv_bfloat162(l2, l3);
}

// ---------------- persistent GRU recurrence (R7-proven, 1251us config) ----------------
__global__ void __launch_bounds__(256, 1)
recurrence_kernel(const float* __restrict__ Whh_e, const float* __restrict__ bhh_e,
                  const float* __restrict__ Whh_d, const float* __restrict__ bhh_d) {
    extern __shared__ float sm[];
    float* we   = sm;                  // [12][512] = 6144
    float* wd   = we + 6144;           // 6144
    float* hs   = wd + 6144;           // [16][520] = 8320
    float* red  = hs + 8320;           // [192][68] = 13056
    float* red2 = red + 13056;         // [3][64] = 192

    const int tid = threadIdx.x;
    const int cta = blockIdx.x;
    const int jbase = cta * 4;
    const int jj = tid >> 6, ks = tid & 63;

    for (int v = tid; v < 12 * 128; v += 256) {
        int r = v >> 7, c = v & 127;
        int g = r >> 2, j2 = r & 3;
        long src = ((long)(g * H_ + jbase + j2) * H_) / 4 + c;
        ((float4*)we)[r * 128 + c] = ((const float4*)Whh_e)[src];
        ((float4*)wd)[r * 128 + c] = ((const float4*)Whh_d)[src];
    }

    const int o = tid;
    const int og = o >> 6, ojj = (o & 63) >> 4, ob = o & 15;
    float obe = 0.f, obd = 0.f;
    if (o < 192) {
        int oj = jbase + ojj;
        obe = bhh_e[og * H_ + oj];
        obd = bhh_d[og * H_ + oj];
    }
    const int fjj = tid >> 4, fb = tid & 15;
    const int fj = jbase + fjj;

    for (int v = tid; v < 8320; v += 256) hs[v] = 0.f;
    __syncthreads();

    int cur = 0;
    for (int step = 0; step < 127; step++) {
        const int enc = (step < 64);
        const int t = enc ? step : step - 64;

        float gi0 = 0.f, gi1 = 0.f, gi2 = 0.f;
        if (tid < 64) {
            const float* gi = enc ? &g_gi_enc[(long)(fb * S_ + t) * H3_]
                                  : &g_gi_dec[(long)(fb * TM1_ + t) * H3_];
            gi0 = __ldcg(&gi[fj]);
            gi1 = __ldcg(&gi[H_ + fj]);
            gi2 = __ldcg(&gi[2 * H_ + fj]);
        }
        if (step > 0) {
            for (int v = tid; v < 2048; v += 256) {
                int bb = v >> 7, c4 = v & 127;
                float4 hv = __ldcg(((const float4*)g_h[cur]) + v);
                *(float4*)&hs[bb * 520 + c4 * 4] = hv;
            }
        }
        __syncthreads();

        const float* W = enc ? we : wd;
        float a0[16], a1[16], a2[16];
#pragma unroll
        for (int b = 0; b < 16; b++) { a0[b] = 0.f; a1[b] = 0.f; a2[b] = 0.f; }

#pragma unroll
        for (int c = 0; c < 2; c++) {
            const int k0 = c * 256 + ks * 4;
            float4 w0 = *(const float4*)&W[(0 * 4 + jj) * 512 + k0];
            float4 w1 = *(const float4*)&W[(1 * 4 + jj) * 512 + k0];
            float4 w2 = *(const float4*)&W[(2 * 4 + jj) * 512 + k0];
#pragma unroll
            for (int b = 0; b < 16; b++) {
                float4 hv = *(const float4*)&hs[b * 520 + k0];
                a0[b] += w0.x * hv.x + w0.y * hv.y + w0.z * hv.z + w0.w * hv.w;
                a1[b] += w1.x * hv.x + w1.y * hv.y + w1.z * hv.z + w1.w * hv.w;
                a2[b] += w2.x * hv.x + w2.y * hv.y + w2.z * hv.z + w2.w * hv.w;
            }
        }

#pragma unroll
        for (int b = 0; b < 16; b++) {
            red[((0 * 4 + jj) * 16 + b) * 68 + ks] = a0[b];
            red[((1 * 4 + jj) * 16 + b) * 68 + ks] = a1[b];
            red[((2 * 4 + jj) * 16 + b) * 68 + ks] = a2[b];
        }
        __syncthreads();

        if (o < 192) {
            const float* rp = &red[o * 68];
            float4 s4 = make_float4(0.f, 0.f, 0.f, 0.f);
#pragma unroll
            for (int i = 0; i < 16; i++) {
                float4 v = *(const float4*)&rp[i * 4];
                s4.x += v.x; s4.y += v.y; s4.z += v.z; s4.w += v.w;
            }
            float s = (s4.x + s4.y) + (s4.z + s4.w);
            red2[og * 64 + ojj * 16 + ob] = s + (enc ? obe : obd);
        }
        __syncthreads();

        if (tid < 64) {
            float hr = red2[0 * 64 + tid];
            float hz = red2[1 * 64 + tid];
            float hn = red2[2 * 64 + tid];
            float r = 1.f / (1.f + expf(-(gi0 + hr)));
            float z = 1.f / (1.f + expf(-(gi1 + hz)));
            float n = tanhf(gi2 + r * hn);
            float hprev = hs[fb * 520 + fj];
            float h = (1.f - z) * n + z * hprev;
            g_h[cur ^ 1][fb * H_ + fj] = h;
            if (enc) g_enc_out[(long)(fb * S_ + t) * H_ + fj] = h;
            else     g_cat[(long)(fb * TM1_ + t) * 2 * H_ + fj] = h;
        }
        cur ^= 1;
        if (step != 126) grid_bar();
    }
}

// ---------------- batched attention (R2-proven) ----------------
__global__ void attn_batch() {
    __shared__ float hsh[H_];
    __shared__ float sc[S_];
    __shared__ float wgt[S_];
    int row = blockIdx.x;
    int b = row / TM1_;
    int tid = threadIdx.x;
    const float* enc = g_enc_out + (long)b * S_ * H_;
    const float* hrow = &g_cat[(long)row * 2 * H_];

    for (int v = tid; v < H_; v += 256) hsh[v] = hrow[v];
    __syncthreads();

    int s = tid >> 2, q = tid & 3;
    {
        const float* e = enc + s * H_ + q * 128;
        const float* hq = hsh + q * 128;
        float p = 0.f;
#pragma unroll
        for (int k = 0; k < 128; k += 4) {
            float4 ev = *(const float4*)&e[k];
            float4 hv = *(const float4*)&hq[k];
            p += ev.x * hv.x + ev.y * hv.y + ev.z * hv.z + ev.w * hv.w;
        }
        p += __shfl_xor_sync(0xffffffffu, p, 1);
        p += __shfl_xor_sync(0xffffffffu, p, 2);
        if (q == 0) sc[s] = p;
    }
    __syncthreads();
    if (tid < 32) {
        float a0 = sc[tid], a1 = sc[tid + 32];
        float m = fmaxf(a0, a1);
        for (int o = 16; o; o >>= 1) m = fmaxf(m, __shfl_xor_sync(0xffffffffu, m, o));
        float e0 = expf(a0 - m), e1 = expf(a1 - m);
        float ss = e0 + e1;
        for (int o = 16; o; o >>= 1) ss += __shfl_xor_sync(0xffffffffu, ss, o);
        wgt[tid] = e0 / ss;
        wgt[tid + 32] = e1 / ss;
    }
    __syncthreads();
    {
        int k = tid, k2 = tid + 256;
        float acc = 0.f, acc2 = 0.f;
#pragma unroll 8
        for (int s2 = 0; s2 < S_; s2++) {
            float w = wgt[s2];
            acc  += w * enc[s2 * H_ + k];
            acc2 += w * enc[s2 * H_ + k2];
        }
        g_cat[(long)row * 2 * H_ + H_ + k]  = acc;
        g_cat[(long)row * 2 * H_ + H_ + k2] = acc2;
    }
}

// ---------------- mma.sync helpers ----------------
__device__ __forceinline__ void ldm_x4(unsigned& r0, unsigned& r1, unsigned& r2, unsigned& r3,
                                       unsigned addr) {
    asm volatile("ldmatrix.sync.aligned.m8n8.x4.shared.b16 {%0,%1,%2,%3}, [%4];"
                 : "=r"(r0), "=r"(r1), "=r"(r2), "=r"(r3) : "r"(addr));
}
__device__ __forceinline__ void ldm_x2(unsigned& r0, unsigned& r1, unsigned addr) {
    asm volatile("ldmatrix.sync.aligned.m8n8.x2.shared.b16 {%0,%1}, [%2];"
                 : "=r"(r0), "=r"(r1) : "r"(addr));
}
__device__ __forceinline__ void mma_bf16(float* c, const unsigned* a, const unsigned* b) {
    asm volatile("mma.sync.aligned.m16n8k16.row.col.f32.bf16.bf16.f32 "
                 "{%0,%1,%2,%3}, {%4,%5,%6,%7}, {%8,%9}, {%0,%1,%2,%3};"
                 : "+f"(c[0]), "+f"(c[1]), "+f"(c[2]), "+f"(c[3])
                 : "r"(a[0]), "r"(a[1]), "r"(a[2]), "r"(a[3]), "r"(b[0]), "r"(b[1]));
}

// ---------------- generic split-bf16 GEMM (generalized from R4-proven mma_logits) ----
// C[M,N] = act( Ah*Bh^T + Ah*Bl^T + Al*Bh^T + bias ), tiles 128x128, K chunks of 32.
#define LPAD 40
__global__ void __launch_bounds__(256, 1)
mma_gemm(const __nv_bfloat16* __restrict__ Agh, const __nv_bfloat16* __restrict__ Agl,
         const __nv_bfloat16* __restrict__ Bgh, const __nv_bfloat16* __restrict__ Bgl,
         const float* __restrict__ bias, float* __restrict__ C,
         int K, int ldC, int Mb, int act) {
    extern __shared__ __nv_bfloat16 smem_bf[];
    __nv_bfloat16* Ah = smem_bf;                    // [2][128*LPAD]
    __nv_bfloat16* Al = Ah + 2 * 128 * LPAD;
    __nv_bfloat16* Bh = Al + 2 * 128 * LPAD;
    __nv_bfloat16* Bl = Bh + 2 * 128 * LPAD;

    const int tid = threadIdx.x;
    const int warp = tid >> 5, lane = tid & 31;
    const int wm = warp >> 2, wn = warp & 3;
    const int m0 = blockIdx.y * 128, n0 = blockIdx.x * 128;
    const int NC = K >> 5;

    const int lrow = tid >> 1;
    const int lcol = (tid & 1) * 16;

    const __nv_bfloat16* Ahp = Agh + (long)(m0 + lrow) * K + lcol;
    const __nv_bfloat16* Alp = Agl + (long)(m0 + lrow) * K + lcol;
    const __nv_bfloat16* Bhp = Bgh + (long)(n0 + lrow) * K + lcol;
    const __nv_bfloat16* Blp = Bgl + (long)(n0 + lrow) * K + lcol;
    const int sdst = lrow * LPAD + lcol;

    float acc[4][4][4];
#pragma unroll
    for (int i = 0; i < 4; i++)
#pragma unroll
        for (int j = 0; j < 4; j++)
#pragma unroll
            for (int q = 0; q < 4; q++) acc[i][j][q] = 0.f;

    uint4 rAh[2], rAl[2], rBh[2], rBl[2];
#pragma unroll
    for (int u = 0; u < 2; u++) {
        rAh[u] = *(const uint4*)(Ahp + u * 8);
        rAl[u] = *(const uint4*)(Alp + u * 8);
        rBh[u] = *(const uint4*)(Bhp + u * 8);
        rBl[u] = *(const uint4*)(Blp + u * 8);
    }
#pragma unroll
    for (int u = 0; u < 2; u++) {
        *(uint4*)&Ah[sdst + u * 8] = rAh[u];
        *(uint4*)&Al[sdst + u * 8] = rAl[u];
        *(uint4*)&Bh[sdst + u * 8] = rBh[u];
        *(uint4*)&Bl[sdst + u * 8] = rBl[u];
    }
    __syncthreads();

    const int a_row = lane & 15, a_colh = (lane >> 4) * 8;
    const int b_row = lane & 7,  b_colh = ((lane >> 3) & 1) * 8;

    for (int c = 0; c < NC; c++) {
        const int buf = c & 1;
        if (c + 1 < NC) {
            const int ko = (c + 1) * 32;
#pragma unroll
            for (int u = 0; u < 2; u++) {
                rAh[u] = *(const uint4*)(Ahp + ko + u * 8);
                rAl[u] = *(const uint4*)(Alp + ko + u * 8);
                rBh[u] = *(const uint4*)(Bhp + ko + u * 8);
                rBl[u] = *(const uint4*)(Blp + ko + u * 8);
            }
        }

        const __nv_bfloat16* Ahb = Ah + buf * 128 * LPAD;
        const __nv_bfloat16* Alb = Al + buf * 128 * LPAD;
        const __nv_bfloat16* Bhb = Bh + buf * 128 * LPAD;
        const __nv_bfloat16* Blb = Bl + buf * 128 * LPAD;

#pragma unroll
        for (int kk = 0; kk < 32; kk += 16) {
            unsigned fAh[4][4], fAl[4][4], fBh[4][2], fBl[4][2];
#pragma unroll
            for (int mi = 0; mi < 4; mi++) {
                int r = wm * 64 + mi * 16 + a_row;
                unsigned ah = (unsigned)__cvta_generic_to_shared(&Ahb[r * LPAD + kk + a_colh]);
                unsigned al = (unsigned)__cvta_generic_to_shared(&Alb[r * LPAD + kk + a_colh]);
                ldm_x4(fAh[mi][0], fAh[mi][1], fAh[mi][2], fAh[mi][3], ah);
                ldm_x4(fAl[mi][0], fAl[mi][1], fAl[mi][2], fAl[mi][3], al);
            }
#pragma unroll
            for (int ni = 0; ni < 4; ni++) {
                int r = wn * 32 + ni * 8 + b_row;
                unsigned bh = (unsigned)__cvta_generic_to_shared(&Bhb[r * LPAD + kk + b_colh]);
                unsigned bl = (unsigned)__cvta_generic_to_shared(&Blb[r * LPAD + kk + b_colh]);
                ldm_x2(fBh[ni][0], fBh[ni][1], bh);
                ldm_x2(fBl[ni][0], fBl[ni][1], bl);
            }
#pragma unroll
            for (int mi = 0; mi < 4; mi++)
#pragma unroll
                for (int ni = 0; ni < 4; ni++) {
                    mma_bf16(acc[mi][ni], fAh[mi], fBh[ni]);
                    mma_bf16(acc[mi][ni], fAh[mi], fBl[ni]);
                    mma_bf16(acc[mi][ni], fAl[mi], fBh[ni]);
                }
        }
        __syncthreads();
        if (c + 1 < NC) {
            const int nb = (c + 1) & 1;
            __nv_bfloat16* dAh = Ah + nb * 128 * LPAD;
            __nv_bfloat16* dAl = Al + nb * 128 * LPAD;
            __nv_bfloat16* dBh = Bh + nb * 128 * LPAD;
            __nv_bfloat16* dBl = Bl + nb * 128 * LPAD;
#pragma unroll
            for (int u = 0; u < 2; u++) {
                *(uint4*)&dAh[sdst + u * 8] = rAh[u];
                *(uint4*)&dAl[sdst + u * 8] = rAl[u];
                *(uint4*)&dBh[sdst + u * 8] = rBh[u];
                *(uint4*)&dBl[sdst + u * 8] = rBl[u];
            }
            __syncthreads();
        }
    }

#pragma unroll
    for (int ni = 0; ni < 4; ni++) {
        int col = n0 + wn * 32 + ni * 8 + (lane & 3) * 2;
        float2 bj = *(const float2*)&bias[col];
#pragma unroll
        for (int mi = 0; mi < 4; mi++) {
            int r0 = m0 + wm * 64 + mi * 16 + (lane >> 2);
            if (r0 < Mb) {
                float2 v = make_float2(acc[mi][ni][0] + bj.x, acc[mi][ni][1] + bj.y);
                if (act) { v.x = tanhf(v.x); v.y = tanhf(v.y); }
                *(float2*)&C[(long)r0 * ldC + col] = v;
            }
            int r1 = r0 + 8;
            if (r1 < Mb) {
                float2 v = make_float2(acc[mi][ni][2] + bj.x, acc[mi][ni][3] + bj.y);
                if (act) { v.x = tanhf(v.x); v.y = tanhf(v.y); }
                *(float2*)&C[(long)r1 * ldC + col] = v;
            }
        }
    }
}

// ---------------- loss: single-pass online softmax NLL ----------------
__global__ void nll_rows(const float* __restrict__ logits, const int* __restrict__ y) {
    __shared__ float mred[256], sred[256];
    int row = blockIdx.x;
    int b = row / TM1_, t = row % TM1_;
    int tgt = y[b * T_ + t + 1];
    const float* L = logits + (long)row * V_;

    float m = -INFINITY, s = 0.f;
    for (int i = threadIdx.x * 4; i < V_; i += 1024) {
        float4 v4 = __ldcg((const float4*)&L[i]);
        float vv[4] = {v4.x, v4.y, v4.z, v4.w};
#pragma unroll
        for (int q = 0; q < 4; q++) {
            float v = vv[q];
            if (v > m) { s *= expf(m - v); m = v; }
            s += expf(v - m);
        }
    }
    mred[threadIdx.x] = m; sred[threadIdx.x] = s;
    __syncthreads();
    for (int o = 128; o; o >>= 1) {
        if (threadIdx.x < o) {
            float m1 = mred[threadIdx.x], s1 = sred[threadIdx.x];
            float m2 = mred[threadIdx.x + o], s2 = sred[threadIdx.x + o];
            float M = fmaxf(m1, m2);
            mred[threadIdx.x] = M;
            sred[threadIdx.x] = s1 * expf(m1 - M) + s2 * expf(m2 - M);
        }
        __syncthreads();
    }
    if (threadIdx.x == 0) g_rownll[row] = logf(sred[0]) + mred[0] - L[tgt];
}

__global__ void loss_reduce(float* __restrict__ out) {
    __shared__ float red[256];
    float ss = 0.f;
    for (int i = threadIdx.x; i < MD_; i += 256) ss += g_rownll[i];
    red[threadIdx.x] = ss;
    __syncthreads();
    for (int o = 128; o; o >>= 1) {
        if (threadIdx.x < o) red[threadIdx.x] += red[threadIdx.x + o];
        __syncthreads();
    }
    if (threadIdx.x == 0) out[0] = red[0] / (float)MD_;
}

// ---------------- host ----------------
static inline int cs_grid(long total) { return (int)((total / 4 + 255) / 256); }

extern "C" void kernel_launch(void* const* d_in, const int* in_sizes, int n_in,
                              void* d_out, int out_size) {
    const int*   x       = (const int*)d_in[0];
    const int*   y       = (const int*)d_in[1];
    const float* emb_enc = (const float*)d_in[2];
    const float* W_ih_e  = (const float*)d_in[3];
    const float* W_hh_e  = (const float*)d_in[4];
    const float* b_ih_e  = (const float*)d_in[5];
    const float* b_hh_e  = (const float*)d_in[6];
    const float* emb_dec = (const float*)d_in[7];
    const float* W_ih_d  = (const float*)d_in[8];
    const float* W_hh_d  = (const float*)d_in[9];
    const float* b_ih_d  = (const float*)d_in[10];
    const float* b_hh_d  = (const float*)d_in[11];
    const float* W_c     = (const float*)d_in[12];
    const float* b_c     = (const float*)d_in[13];
    const float* W_out   = (const float*)d_in[14];
    const float* b_out   = (const float*)d_in[15];
    float* out = (float*)d_out;

    const int mma_smem = 8 * 128 * LPAD * sizeof(__nv_bfloat16);  // 81920 B
    cudaFuncSetAttribute(mma_gemm, cudaFuncAttributeMaxDynamicSharedMemorySize, mma_smem);

    // device-global raw pointers (host-side symbol addresses)
    __nv_bfloat16 *exh, *exl, *eyh, *eyl, *wieh, *wiel, *widh, *widl;
    __nv_bfloat16 *wch, *wcl, *cath, *catl, *whi, *wlo, *dhi, *dlo;
    float *p_emb_x, *p_emb_y, *p_cat, *p_dseq, *p_gi_enc, *p_gi_dec;
    cudaGetSymbolAddress((void**)&exh,  g_exh);  cudaGetSymbolAddress((void**)&exl,  g_exl);
    cudaGetSymbolAddress((void**)&eyh,  g_eyh);  cudaGetSymbolAddress((void**)&eyl,  g_eyl);
    cudaGetSymbolAddress((void**)&wieh, g_wieh); cudaGetSymbolAddress((void**)&wiel, g_wiel);
    cudaGetSymbolAddress((void**)&widh, g_widh); cudaGetSymbolAddress((void**)&widl, g_widl);
    cudaGetSymbolAddress((void**)&wch,  g_wch);  cudaGetSymbolAddress((void**)&wcl,  g_wcl);
    cudaGetSymbolAddress((void**)&cath, g_cath); cudaGetSymbolAddress((void**)&catl, g_catl);
    cudaGetSymbolAddress((void**)&whi,  g_whi);  cudaGetSymbolAddress((void**)&wlo,  g_wlo);
    cudaGetSymbolAddress((void**)&dhi,  g_dhi);  cudaGetSymbolAddress((void**)&dlo,  g_dlo);
    cudaGetSymbolAddress((void**)&p_emb_x, g_emb_x);
    cudaGetSymbolAddress((void**)&p_emb_y, g_emb_y);
    cudaGetSymbolAddress((void**)&p_cat,   g_cat);
    cudaGetSymbolAddress((void**)&p_dseq,  g_dseq);
    cudaGetSymbolAddress((void**)&p_gi_enc, g_gi_enc);
    cudaGetSymbolAddress((void**)&p_gi_dec, g_gi_dec);

    // 1. embeddings; W_out + W_ih + W_c splits (input-independent of embeds)
    {
        int total = ME_ * H_ + MD_ * H_;
        embed_kernel<<<(total + 255) / 256, 256>>>(x, y, emb_enc, emb_dec);
    }
    convert_split<<<cs_grid((long)V_ * H_), 256>>>(W_out, whi, wlo, V_, (long)V_ * H_, H_);
    convert_split<<<cs_grid((long)H3_ * H_), 256>>>(W_ih_e, wieh, wiel, H3_, (long)H3_ * H_, H_);
    convert_split<<<cs_grid((long)H3_ * H_), 256>>>(W_ih_d, widh, widl, H3_, (long)H3_ * H_, H_);
    convert_split<<<cs_grid((long)H_ * 2 * H_), 256>>>(W_c, wch, wcl, H_, (long)H_ * 2 * H_, 2 * H_);

    // embeddings -> split bf16 (emb_y padded 1008 -> 1024 rows)
    convert_split<<<cs_grid((long)ME_ * H_), 256>>>(p_emb_x, exh, exl, ME_, (long)ME_ * H_, H_);
    convert_split<<<cs_grid((long)MP_ * H_), 256>>>(p_emb_y, eyh, eyl, MD_, (long)MP_ * H_, H_);

    // 2. input-side gate precompute via tensor cores
    mma_gemm<<<dim3(H3_ / 128, ME_ / 128), 256, mma_smem>>>(
        exh, exl, wieh, wiel, b_ih_e, p_gi_enc, H_, H3_, ME_, 0);
    mma_gemm<<<dim3(H3_ / 128, MP_ / 128), 256, mma_smem>>>(
        eyh, eyl, widh, widl, b_ih_d, p_gi_dec, H_, H3_, MD_, 0);

    // 3. persistent recurrence (R7-proven)
    {
        const int smem = (6144 * 2 + 8320 + 13056 + 192) * sizeof(float); // 135808 B
        cudaFuncSetAttribute(recurrence_kernel,
                             cudaFuncAttributeMaxDynamicSharedMemorySize, smem);
        recurrence_kernel<<<NCTA, 256, smem>>>(W_hh_e, b_hh_e, W_hh_d, b_hh_d);
    }

    // 4. batched attention
    attn_batch<<<MD_, 256>>>();

    // 5. concat -> split bf16 (padded), then d = tanh(cat @ W_c^T + b_c) via mma
    convert_split<<<cs_grid((long)MP_ * 2 * H_), 256>>>(p_cat, cath, catl, MD_,
                                                        (long)MP_ * 2 * H_, 2 * H_);
    mma_gemm<<<dim3(H_ / 128, MP_ / 128), 256, mma_smem>>>(
        cath, catl, wch, wcl, b_c, p_dseq, 2 * H_, H_, MD_, 1);

    // 6. d -> split bf16 (padded), then logits GEMM -> d_out
    convert_split<<<cs_grid((long)MP_ * H_), 256>>>(p_dseq, dhi, dlo, MD_, (long)MP_ * H_, H_);
    mma_gemm<<<dim3(V_ / 128, MP_ / 128), 256, mma_smem>>>(
        dhi, dlo, whi, wlo, b_out, out, H_, V_, MD_, 0);

    // 7. loss
    if (out_size >= MD_ * V_ + 1) {
        nll_rows<<<MD_, 256>>>(out, y);
        loss_reduce<<<1, 256>>>(out + (long)MD_ * V_);
    }
}

// round 17
// speedup vs baseline: 1.1368x; 1.0069x over previous
#include <cuda_runtime.h>
#include <cuda_bf16.h>
#include <math.h>

#define B_   16
#define S_   64
#define T_   64
#define TM1_ 63
#define H_   512
#define H3_  1536
#define V_   32000
#define ME_  (B_*S_)     // 1024 encoder rows
#define MD_  (B_*TM1_)   // 1008 decoder rows
#define MP_  1024        // padded M for MMA
#define NCTA 128

// ---------------- device scratch (no allocation allowed) ----------------
__device__ float g_gi_enc[ME_*H3_];
__device__ float g_gi_dec[MD_*H3_];
__device__ float g_enc_out[ME_*H_];
__device__ float g_h[2][B_*H_];
__device__ float g_cat[MD_*2*H_];
__device__ float g_rownll[MD_];

// split-bf16 operand buffers (zero-initialized; padded rows never written)
__device__ __nv_bfloat16 g_whi[(long)V_*H_], g_wlo[(long)V_*H_];     // W_out
__device__ __nv_bfloat16 g_dhi[MP_*H_],      g_dlo[MP_*H_];          // d (padded)
__device__ __nv_bfloat16 g_exh[ME_*H_],      g_exl[ME_*H_];          // emb_x
__device__ __nv_bfloat16 g_eyh[MP_*H_],      g_eyl[MP_*H_];          // emb_y (padded)
__device__ __nv_bfloat16 g_wieh[H3_*H_],     g_wiel[H3_*H_];         // W_ih_e
__device__ __nv_bfloat16 g_widh[H3_*H_],     g_widl[H3_*H_];         // W_ih_d
__device__ __nv_bfloat16 g_wch[H_*2*H_],     g_wcl[H_*2*H_];         // W_c
__device__ __nv_bfloat16 g_cath[MP_*2*H_],   g_catl[MP_*2*H_];       // concat (padded)

__device__ unsigned g_cnt = 0;
__device__ unsigned g_gen = 0;

// ---------------- split helper ----------------
__device__ __forceinline__ void split_bf(float x, __nv_bfloat16& hi, __nv_bfloat16& lo) {
    hi = __float2bfloat16_rn(x);
    lo = __float2bfloat16_rn(x - __bfloat162float(hi));
}

// ---------------- software grid barrier (R7-proven flat version) ----------------
__device__ __forceinline__ void grid_bar() {
    __threadfence();
    __syncthreads();
    if (threadIdx.x == 0) {
        unsigned g = *(volatile unsigned*)&g_gen;
        if (atomicAdd(&g_cnt, 1u) == NCTA - 1) {
            g_cnt = 0;
            __threadfence();
            atomicExch(&g_gen, g + 1u);
        } else {
            while (*(volatile unsigned*)&g_gen == g) __nanosleep(32);
        }
        __threadfence();
    }
    __syncthreads();
}

// ---------------- embedding gather + direct bf16 split ----------------
__global__ void embed_kernel(const int* __restrict__ x, const int* __restrict__ y,
                             const float* __restrict__ emb_enc,
                             const float* __restrict__ emb_dec) {
    int i = blockIdx.x * blockDim.x + threadIdx.x;
    const int n1 = ME_ * H_;
    const int n2 = MD_ * H_;
    if (i < n1) {
        int row = i / H_, h = i % H_;
        float v = emb_enc[(long)x[row] * H_ + h];
        __nv_bfloat16 hi, lo;
        split_bf(v, hi, lo);
        g_exh[i] = hi;
        g_exl[i] = lo;
    } else if (i < n1 + n2) {
        int j = i - n1;
        int row = j / H_, h = j % H_;
        int b = row / TM1_, t = row % TM1_;
        float v = emb_dec[(long)y[b * T_ + t] * H_ + h];
        __nv_bfloat16 hi, lo;
        split_bf(v, hi, lo);
        g_eyh[j] = hi;
        g_eyl[j] = lo;
    }
}

// ---------------- generic split-bf16 conversion (weights, cat) ----------------
__global__ void convert_split(const float* __restrict__ src,
                              __nv_bfloat16* __restrict__ hi,
                              __nv_bfloat16* __restrict__ lo,
                              int rows_src, long total, int cols) {
    long i = ((long)blockIdx.x * blockDim.x + threadIdx.x) * 4;
    if (i >= total) return;
    int row = (int)(i / cols);
    float4 v = make_float4(0.f, 0.f, 0.f, 0.f);
    if (row < rows_src) v = *(const float4*)&src[i];
    __nv_bfloat16 h0, h1, h2, h3, l0, l1, l2, l3;
    split_bf(v.x, h0, l0); split_bf(v.y, h1, l1);
    split_bf(v.z, h2, l2); split_bf(v.w, h3, l3);
    *(__nv_bfloat162*)&hi[i]     = __nv_bfloat162(h0, h1);
    *(__nv_bfloat162*)&hi[i + 2] = __nv_bfloat162(h2, h3);
    *(__nv_bfloat162*)&lo[i]     = __nv_bfloat162(l0, l1);
    *(__nv_bfloat162*)&lo[i + 2] = __nv_bfloat162(l2, l3);
}

// ---------------- persistent GRU recurrence (R7-proven, unchanged) ----------------
__global__ void __launch_bounds__(256, 1)
recurrence_kernel(const float* __restrict__ Whh_e, const float* __restrict__ bhh_e,
                  const float* __restrict__ Whh_d, const float* __restrict__ bhh_d) {
    extern __shared__ float sm[];
    float* we   = sm;                  // [12][512]
    float* wd   = we + 6144;
    float* hs   = wd + 6144;           // [16][520]
    float* red  = hs + 8320;           // [192][68]
    float* red2 = red + 13056;         // [3][64]

    const int tid = threadIdx.x;
    const int cta = blockIdx.x;
    const int jbase = cta * 4;
    const int jj = tid >> 6, ks = tid & 63;

    for (int v = tid; v < 12 * 128; v += 256) {
        int r = v >> 7, c = v & 127;
        int g = r >> 2, j2 = r & 3;
        long src = ((long)(g * H_ + jbase + j2) * H_) / 4 + c;
        ((float4*)we)[r * 128 + c] = ((const float4*)Whh_e)[src];
        ((float4*)wd)[r * 128 + c] = ((const float4*)Whh_d)[src];
    }

    const int o = tid;
    const int og = o >> 6, ojj = (o & 63) >> 4, ob = o & 15;
    float obe = 0.f, obd = 0.f;
    if (o < 192) {
        int oj = jbase + ojj;
        obe = bhh_e[og * H_ + oj];
        obd = bhh_d[og * H_ + oj];
    }
    const int fjj = tid >> 4, fb = tid & 15;
    const int fj = jbase + fjj;

    for (int v = tid; v < 8320; v += 256) hs[v] = 0.f;
    __syncthreads();

    int cur = 0;
    for (int step = 0; step < 127; step++) {
        const int enc = (step < 64);
        const int t = enc ? step : step - 64;

        float gi0 = 0.f, gi1 = 0.f, gi2 = 0.f;
        if (tid < 64) {
            const float* gi = enc ? &g_gi_enc[(long)(fb * S_ + t) * H3_]
                                  : &g_gi_dec[(long)(fb * TM1_ + t) * H3_];
            gi0 = __ldcg(&gi[fj]);
            gi1 = __ldcg(&gi[H_ + fj]);
            gi2 = __ldcg(&gi[2 * H_ + fj]);
        }
        if (step > 0) {
            for (int v = tid; v < 2048; v += 256) {
                int bb = v >> 7, c4 = v & 127;
                float4 hv = __ldcg(((const float4*)g_h[cur]) + v);
                *(float4*)&hs[bb * 520 + c4 * 4] = hv;
            }
        }
        __syncthreads();

        const float* W = enc ? we : wd;
        float a0[16], a1[16], a2[16];
#pragma unroll
        for (int b = 0; b < 16; b++) { a0[b] = 0.f; a1[b] = 0.f; a2[b] = 0.f; }

#pragma unroll
        for (int c = 0; c < 2; c++) {
            const int k0 = c * 256 + ks * 4;
            float4 w0 = *(const float4*)&W[(0 * 4 + jj) * 512 + k0];
            float4 w1 = *(const float4*)&W[(1 * 4 + jj) * 512 + k0];
            float4 w2 = *(const float4*)&W[(2 * 4 + jj) * 512 + k0];
#pragma unroll
            for (int b = 0; b < 16; b++) {
                float4 hv = *(const float4*)&hs[b * 520 + k0];
                a0[b] += w0.x * hv.x + w0.y * hv.y + w0.z * hv.z + w0.w * hv.w;
                a1[b] += w1.x * hv.x + w1.y * hv.y + w1.z * hv.z + w1.w * hv.w;
                a2[b] += w2.x * hv.x + w2.y * hv.y + w2.z * hv.z + w2.w * hv.w;
            }
        }

#pragma unroll
        for (int b = 0; b < 16; b++) {
            red[((0 * 4 + jj) * 16 + b) * 68 + ks] = a0[b];
            red[((1 * 4 + jj) * 16 + b) * 68 + ks] = a1[b];
            red[((2 * 4 + jj) * 16 + b) * 68 + ks] = a2[b];
        }
        __syncthreads();

        if (o < 192) {
            const float* rp = &red[o * 68];
            float4 s4 = make_float4(0.f, 0.f, 0.f, 0.f);
#pragma unroll
            for (int i = 0; i < 16; i++) {
                float4 v = *(const float4*)&rp[i * 4];
                s4.x += v.x; s4.y += v.y; s4.z += v.z; s4.w += v.w;
            }
            float s = (s4.x + s4.y) + (s4.z + s4.w);
            red2[og * 64 + ojj * 16 + ob] = s + (enc ? obe : obd);
        }
        __syncthreads();

        if (tid < 64) {
            float hr = red2[0 * 64 + tid];
            float hz = red2[1 * 64 + tid];
            float hn = red2[2 * 64 + tid];
            float r = 1.f / (1.f + expf(-(gi0 + hr)));
            float z = 1.f / (1.f + expf(-(gi1 + hz)));
            float n = tanhf(gi2 + r * hn);
            float hprev = hs[fb * 520 + fj];
            float h = (1.f - z) * n + z * hprev;
            g_h[cur ^ 1][fb * H_ + fj] = h;
            if (enc) g_enc_out[(long)(fb * S_ + t) * H_ + fj] = h;
            else     g_cat[(long)(fb * TM1_ + t) * 2 * H_ + fj] = h;
        }
        cur ^= 1;
        if (step != 126) grid_bar();
    }
}

// ---------------- batched attention (R2-proven) ----------------
__global__ void attn_batch() {
    __shared__ float hsh[H_];
    __shared__ float sc[S_];
    __shared__ float wgt[S_];
    int row = blockIdx.x;
    int b = row / TM1_;
    int tid = threadIdx.x;
    const float* enc = g_enc_out + (long)b * S_ * H_;
    const float* hrow = &g_cat[(long)row * 2 * H_];

    for (int v = tid; v < H_; v += 256) hsh[v] = hrow[v];
    __syncthreads();

    int s = tid >> 2, q = tid & 3;
    {
        const float* e = enc + s * H_ + q * 128;
        const float* hq = hsh + q * 128;
        float p = 0.f;
#pragma unroll
        for (int k = 0; k < 128; k += 4) {
            float4 ev = *(const float4*)&e[k];
            float4 hv = *(const float4*)&hq[k];
            p += ev.x * hv.x + ev.y * hv.y + ev.z * hv.z + ev.w * hv.w;
        }
        p += __shfl_xor_sync(0xffffffffu, p, 1);
        p += __shfl_xor_sync(0xffffffffu, p, 2);
        if (q == 0) sc[s] = p;
    }
    __syncthreads();
    if (tid < 32) {
        float a0 = sc[tid], a1 = sc[tid + 32];
        float m = fmaxf(a0, a1);
        for (int o = 16; o; o >>= 1) m = fmaxf(m, __shfl_xor_sync(0xffffffffu, m, o));
        float e0 = expf(a0 - m), e1 = expf(a1 - m);
        float ss = e0 + e1;
        for (int o = 16; o; o >>= 1) ss += __shfl_xor_sync(0xffffffffu, ss, o);
        wgt[tid] = e0 / ss;
        wgt[tid + 32] = e1 / ss;
    }
    __syncthreads();
    {
        int k = tid, k2 = tid + 256;
        float acc = 0.f, acc2 = 0.f;
#pragma unroll 8
        for (int s2 = 0; s2 < S_; s2++) {
            float w = wgt[s2];
            acc  += w * enc[s2 * H_ + k];
            acc2 += w * enc[s2 * H_ + k2];
        }
        g_cat[(long)row * 2 * H_ + H_ + k]  = acc;
        g_cat[(long)row * 2 * H_ + H_ + k2] = acc2;
    }
}

// ---------------- mma.sync helpers ----------------
__device__ __forceinline__ void ldm_x4(unsigned& r0, unsigned& r1, unsigned& r2, unsigned& r3,
                                       unsigned addr) {
    asm volatile("ldmatrix.sync.aligned.m8n8.x4.shared.b16 {%0,%1,%2,%3}, [%4];"
                 : "=r"(r0), "=r"(r1), "=r"(r2), "=r"(r3) : "r"(addr));
}
__device__ __forceinline__ void ldm_x2(unsigned& r0, unsigned& r1, unsigned addr) {
    asm volatile("ldmatrix.sync.aligned.m8n8.x2.shared.b16 {%0,%1}, [%2];"
                 : "=r"(r0), "=r"(r1) : "r"(addr));
}
__device__ __forceinline__ void mma_bf16(float* c, const unsigned* a, const unsigned* b) {
    asm volatile("mma.sync.aligned.m16n8k16.row.col.f32.bf16.bf16.f32 "
                 "{%0,%1,%2,%3}, {%4,%5,%6,%7}, {%8,%9}, {%0,%1,%2,%3};"
                 : "+f"(c[0]), "+f"(c[1]), "+f"(c[2]), "+f"(c[3])
                 : "r"(a[0]), "r"(a[1]), "r"(a[2]), "r"(a[3]), "r"(b[0]), "r"(b[1]));
}

// ---------------- generic split-bf16 GEMM (R11-proven) ----------------
// C[M,N] = act( Ah*Bh^T + Ah*Bl^T + Al*Bh^T + bias ). 128x128 tiles, K chunks of 32.
// dsplit: epilogue applies tanh and writes bf16 split to g_dhi/g_dlo instead of C.
#define LPAD 40
__global__ void __launch_bounds__(256, 1)
mma_gemm(const __nv_bfloat16* __restrict__ Agh, const __nv_bfloat16* __restrict__ Agl,
         const __nv_bfloat16* __restrict__ Bgh, const __nv_bfloat16* __restrict__ Bgl,
         const float* __restrict__ bias, float* __restrict__ C,
         int K, int ldC, int Mb, int act, int dsplit) {
    extern __shared__ __nv_bfloat16 smem_bf[];
    __nv_bfloat16* Ah = smem_bf;
    __nv_bfloat16* Al = Ah + 2 * 128 * LPAD;
    __nv_bfloat16* Bh = Al + 2 * 128 * LPAD;
    __nv_bfloat16* Bl = Bh + 2 * 128 * LPAD;

    const int tid = threadIdx.x;
    const int warp = tid >> 5, lane = tid & 31;
    const int wm = warp >> 2, wn = warp & 3;
    const int m0 = blockIdx.y * 128, n0 = blockIdx.x * 128;
    const int NC = K >> 5;

    const int lrow = tid >> 1;
    const int lcol = (tid & 1) * 16;

    const __nv_bfloat16* Ahp = Agh + (long)(m0 + lrow) * K + lcol;
    const __nv_bfloat16* Alp = Agl + (long)(m0 + lrow) * K + lcol;
    const __nv_bfloat16* Bhp = Bgh + (long)(n0 + lrow) * K + lcol;
    const __nv_bfloat16* Blp = Bgl + (long)(n0 + lrow) * K + lcol;
    const int sdst = lrow * LPAD + lcol;

    float acc[4][4][4];
#pragma unroll
    for (int i = 0; i < 4; i++)
#pragma unroll
        for (int j = 0; j < 4; j++)
#pragma unroll
            for (int q = 0; q < 4; q++) acc[i][j][q] = 0.f;

    uint4 rAh[2], rAl[2], rBh[2], rBl[2];
#pragma unroll
    for (int u = 0; u < 2; u++) {
        rAh[u] = *(const uint4*)(Ahp + u * 8);
        rAl[u] = *(const uint4*)(Alp + u * 8);
        rBh[u] = *(const uint4*)(Bhp + u * 8);
        rBl[u] = *(const uint4*)(Blp + u * 8);
    }
#pragma unroll
    for (int u = 0; u < 2; u++) {
        *(uint4*)&Ah[sdst + u * 8] = rAh[u];
        *(uint4*)&Al[sdst + u * 8] = rAl[u];
        *(uint4*)&Bh[sdst + u * 8] = rBh[u];
        *(uint4*)&Bl[sdst + u * 8] = rBl[u];
    }
    __syncthreads();

    const int a_row = lane & 15, a_colh = (lane >> 4) * 8;
    const int b_row = lane & 7,  b_colh = ((lane >> 3) & 1) * 8;

    for (int c = 0; c < NC; c++) {
        const int buf = c & 1;
        if (c + 1 < NC) {
            const int ko = (c + 1) * 32;
#pragma unroll
            for (int u = 0; u < 2; u++) {
                rAh[u] = *(const uint4*)(Ahp + ko + u * 8);
                rAl[u] = *(const uint4*)(Alp + ko + u * 8);
                rBh[u] = *(const uint4*)(Bhp + ko + u * 8);
                rBl[u] = *(const uint4*)(Blp + ko + u * 8);
            }
        }

        const __nv_bfloat16* Ahb = Ah + buf * 128 * LPAD;
        const __nv_bfloat16* Alb = Al + buf * 128 * LPAD;
        const __nv_bfloat16* Bhb = Bh + buf * 128 * LPAD;
        const __nv_bfloat16* Blb = Bl + buf * 128 * LPAD;

#pragma unroll
        for (int kk = 0; kk < 32; kk += 16) {
            unsigned fAh[4][4], fAl[4][4], fBh[4][2], fBl[4][2];
#pragma unroll
            for (int mi = 0; mi < 4; mi++) {
                int r = wm * 64 + mi * 16 + a_row;
                unsigned ah = (unsigned)__cvta_generic_to_shared(&Ahb[r * LPAD + kk + a_colh]);
                unsigned al = (unsigned)__cvta_generic_to_shared(&Alb[r * LPAD + kk + a_colh]);
                ldm_x4(fAh[mi][0], fAh[mi][1], fAh[mi][2], fAh[mi][3], ah);
                ldm_x4(fAl[mi][0], fAl[mi][1], fAl[mi][2], fAl[mi][3], al);
            }
#pragma unroll
            for (int ni = 0; ni < 4; ni++) {
                int r = wn * 32 + ni * 8 + b_row;
                unsigned bh = (unsigned)__cvta_generic_to_shared(&Bhb[r * LPAD + kk + b_colh]);
                unsigned bl = (unsigned)__cvta_generic_to_shared(&Blb[r * LPAD + kk + b_colh]);
                ldm_x2(fBh[ni][0], fBh[ni][1], bh);
                ldm_x2(fBl[ni][0], fBl[ni][1], bl);
            }
#pragma unroll
            for (int mi = 0; mi < 4; mi++)
#pragma unroll
                for (int ni = 0; ni < 4; ni++) {
                    mma_bf16(acc[mi][ni], fAh[mi], fBh[ni]);
                    mma_bf16(acc[mi][ni], fAh[mi], fBl[ni]);
                    mma_bf16(acc[mi][ni], fAl[mi], fBh[ni]);
                }
        }
        __syncthreads();
        if (c + 1 < NC) {
            const int nb = (c + 1) & 1;
            __nv_bfloat16* dAh = Ah + nb * 128 * LPAD;
            __nv_bfloat16* dAl = Al + nb * 128 * LPAD;
            __nv_bfloat16* dBh = Bh + nb * 128 * LPAD;
            __nv_bfloat16* dBl = Bl + nb * 128 * LPAD;
#pragma unroll
            for (int u = 0; u < 2; u++) {
                *(uint4*)&dAh[sdst + u * 8] = rAh[u];
                *(uint4*)&dAl[sdst + u * 8] = rAl[u];
                *(uint4*)&dBh[sdst + u * 8] = rBh[u];
                *(uint4*)&dBl[sdst + u * 8] = rBl[u];
            }
            __syncthreads();
        }
    }

#pragma unroll
    for (int ni = 0; ni < 4; ni++) {
        int col = n0 + wn * 32 + ni * 8 + (lane & 3) * 2;
        float2 bj = *(const float2*)&bias[col];
#pragma unroll
        for (int mi = 0; mi < 4; mi++) {
            int r0 = m0 + wm * 64 + mi * 16 + (lane >> 2);
            int r1 = r0 + 8;
            float2 v0 = make_float2(acc[mi][ni][0] + bj.x, acc[mi][ni][1] + bj.y);
            float2 v1 = make_float2(acc[mi][ni][2] + bj.x, acc[mi][ni][3] + bj.y);
            if (act) {
                v0.x = tanhf(v0.x); v0.y = tanhf(v0.y);
                v1.x = tanhf(v1.x); v1.y = tanhf(v1.y);
            }
            if (dsplit) {
                __nv_bfloat16 h0, l0, h1, l1;
                if (r0 < Mb) {
                    split_bf(v0.x, h0, l0); split_bf(v0.y, h1, l1);
                    *(__nv_bfloat162*)&g_dhi[(long)r0 * ldC + col] = __nv_bfloat162(h0, h1);
                    *(__nv_bfloat162*)&g_dlo[(long)r0 * ldC + col] = __nv_bfloat162(l0, l1);
                }
                if (r1 < Mb) {
                    split_bf(v1.x, h0, l0); split_bf(v1.y, h1, l1);
                    *(__nv_bfloat162*)&g_dhi[(long)r1 * ldC + col] = __nv_bfloat162(h0, h1);
                    *(__nv_bfloat162*)&g_dlo[(long)r1 * ldC + col] = __nv_bfloat162(l0, l1);
                }
            } else {
                if (r0 < Mb) *(float2*)&C[(long)r0 * ldC + col] = v0;
                if (r1 < Mb) *(float2*)&C[(long)r1 * ldC + col] = v1;
            }
        }
    }
}

// ---------------- loss: single-pass online softmax NLL ----------------
__global__ void nll_rows(const float* __restrict__ logits, const int* __restrict__ y) {
    __shared__ float mred[256], sred[256];
    int row = blockIdx.x;
    int b = row / TM1_, t = row % TM1_;
    int tgt = y[b * T_ + t + 1];
    const float* L = logits + (long)row * V_;

    float m = -INFINITY, s = 0.f;
    for (int i = threadIdx.x * 4; i < V_; i += 1024) {
        float4 v4 = __ldcg((const float4*)&L[i]);
        float vv[4] = {v4.x, v4.y, v4.z, v4.w};
#pragma unroll
        for (int q = 0; q < 4; q++) {
            float v = vv[q];
            if (v > m) { s *= expf(m - v); m = v; }
            s += expf(v - m);
        }
    }
    mred[threadIdx.x] = m; sred[threadIdx.x] = s;
    __syncthreads();
    for (int o = 128; o; o >>= 1) {
        if (threadIdx.x < o) {
            float m1 = mred[threadIdx.x], s1 = sred[threadIdx.x];
            float m2 = mred[threadIdx.x + o], s2 = sred[threadIdx.x + o];
            float M = fmaxf(m1, m2);
            mred[threadIdx.x] = M;
            sred[threadIdx.x] = s1 * expf(m1 - M) + s2 * expf(m2 - M);
        }
        __syncthreads();
    }
    if (threadIdx.x == 0) g_rownll[row] = logf(sred[0]) + mred[0] - L[tgt];
}

__global__ void loss_reduce(float* __restrict__ out) {
    __shared__ float red[256];
    float ss = 0.f;
    for (int i = threadIdx.x; i < MD_; i += 256) ss += g_rownll[i];
    red[threadIdx.x] = ss;
    __syncthreads();
    for (int o = 128; o; o >>= 1) {
        if (threadIdx.x < o) red[threadIdx.x] += red[threadIdx.x + o];
        __syncthreads();
    }
    if (threadIdx.x == 0) out[0] = red[0] / (float)MD_;
}

// ---------------- host ----------------
static inline int cs_grid(long total) { return (int)((total / 4 + 255) / 256); }

extern "C" void kernel_launch(void* const* d_in, const int* in_sizes, int n_in,
                              void* d_out, int out_size) {
    const int*   x       = (const int*)d_in[0];
    const int*   y       = (const int*)d_in[1];
    const float* emb_enc = (const float*)d_in[2];
    const float* W_ih_e  = (const float*)d_in[3];
    const float* W_hh_e  = (const float*)d_in[4];
    const float* b_ih_e  = (const float*)d_in[5];
    const float* b_hh_e  = (const float*)d_in[6];
    const float* emb_dec = (const float*)d_in[7];
    const float* W_ih_d  = (const float*)d_in[8];
    const float* W_hh_d  = (const float*)d_in[9];
    const float* b_ih_d  = (const float*)d_in[10];
    const float* b_hh_d  = (const float*)d_in[11];
    const float* W_c     = (const float*)d_in[12];
    const float* b_c     = (const float*)d_in[13];
    const float* W_out   = (const float*)d_in[14];
    const float* b_out   = (const float*)d_in[15];
    float* out = (float*)d_out;

    const int mma_smem = 8 * 128 * LPAD * sizeof(__nv_bfloat16);  // 81920 B
    cudaFuncSetAttribute(mma_gemm, cudaFuncAttributeMaxDynamicSharedMemorySize, mma_smem);

    // device-global raw pointers (host-side symbol addresses; R11-proven pattern)
    __nv_bfloat16 *exh, *exl, *eyh, *eyl, *wieh, *wiel, *widh, *widl;
    __nv_bfloat16 *wch, *wcl, *cath, *catl, *whi, *wlo, *dhi, *dlo;
    float *p_cat, *p_gi_enc, *p_gi_dec;
    cudaGetSymbolAddress((void**)&exh,  g_exh);  cudaGetSymbolAddress((void**)&exl,  g_exl);
    cudaGetSymbolAddress((void**)&eyh,  g_eyh);  cudaGetSymbolAddress((void**)&eyl,  g_eyl);
    cudaGetSymbolAddress((void**)&wieh, g_wieh); cudaGetSymbolAddress((void**)&wiel, g_wiel);
    cudaGetSymbolAddress((void**)&widh, g_widh); cudaGetSymbolAddress((void**)&widl, g_widl);
    cudaGetSymbolAddress((void**)&wch,  g_wch);  cudaGetSymbolAddress((void**)&wcl,  g_wcl);
    cudaGetSymbolAddress((void**)&cath, g_cath); cudaGetSymbolAddress((void**)&catl, g_catl);
    cudaGetSymbolAddress((void**)&whi,  g_whi);  cudaGetSymbolAddress((void**)&wlo,  g_wlo);
    cudaGetSymbolAddress((void**)&dhi,  g_dhi);  cudaGetSymbolAddress((void**)&dlo,  g_dlo);
    cudaGetSymbolAddress((void**)&p_cat,    g_cat);
    cudaGetSymbolAddress((void**)&p_gi_enc, g_gi_enc);
    cudaGetSymbolAddress((void**)&p_gi_dec, g_gi_dec);

    // 1. embeddings (direct bf16 split) + weight splits
    {
        int total = ME_ * H_ + MD_ * H_;
        embed_kernel<<<(total + 255) / 256, 256>>>(x, y, emb_enc, emb_dec);
    }
    convert_split<<<cs_grid((long)V_ * H_), 256>>>(W_out, whi, wlo, V_, (long)V_ * H_, H_);
    convert_split<<<cs_grid((long)H3_ * H_), 256>>>(W_ih_e, wieh, wiel, H3_, (long)H3_ * H_, H_);
    convert_split<<<cs_grid((long)H3_ * H_), 256>>>(W_ih_d, widh, widl, H3_, (long)H3_ * H_, H_);
    convert_split<<<cs_grid((long)H_ * 2 * H_), 256>>>(W_c, wch, wcl, H_, (long)H_ * 2 * H_, 2 * H_);

    // 2. input-side gate precompute via tensor cores
    mma_gemm<<<dim3(H3_ / 128, ME_ / 128), 256, mma_smem>>>(
        exh, exl, wieh, wiel, b_ih_e, p_gi_enc, H_, H3_, ME_, 0, 0);
    mma_gemm<<<dim3(H3_ / 128, MP_ / 128), 256, mma_smem>>>(
        eyh, eyl, widh, widl, b_ih_d, p_gi_dec, H_, H3_, MD_, 0, 0);

    // 3. persistent recurrence (R7-proven)
    {
        const int smem = (6144 * 2 + 8320 + 13056 + 192) * sizeof(float); // 135808 B
        cudaFuncSetAttribute(recurrence_kernel,
                             cudaFuncAttributeMaxDynamicSharedMemorySize, smem);
        recurrence_kernel<<<NCTA, 256, smem>>>(W_hh_e, b_hh_e, W_hh_d, b_hh_d);
    }

    // 4. batched attention
    attn_batch<<<MD_, 256>>>();

    // 5. concat -> split bf16 (padded), then d = tanh(cat @ W_c^T + b_c)
    //    with fused bf16 split written directly to g_dhi/g_dlo (dsplit=1)
    convert_split<<<cs_grid((long)MP_ * 2 * H_), 256>>>(p_cat, cath, catl, MD_,
                                                        (long)MP_ * 2 * H_, 2 * H_);
    mma_gemm<<<dim3(H_ / 128, MP_ / 128), 256, mma_smem>>>(
        cath, catl, wch, wcl, b_c, nullptr, 2 * H_, H_, MD_, 1, 1);

    // 6. logits GEMM -> d_out
    mma_gemm<<<dim3(V_ / 128, MP_ / 128), 256, mma_smem>>>(
        dhi, dlo, whi, wlo, b_out, out, H_, V_, MD_, 0, 0);

    // 7. loss
    if (out_size >= MD_ * V_ + 1) {
        nll_rows<<<MD_, 256>>>(out, y);
        loss_reduce<<<1, 256>>>(out + (long)MD_ * V_);
    }
}